// round 13
// baseline (speedup 1.0000x reference)
#include <cuda_runtime.h>
#include <cuda_bf16.h>
#include <cstdint>

#define Bb   8
#define Nn   1024
#define Hh   8
#define Dd   128
#define ROWS (Bb*Nn)      // 8192
#define EPSc 1e-5f

typedef unsigned long long ull;

// ---------------- scratch (static; no cudaMalloc) ---------------------------
__device__ float  g_Wt[Dd*Dd];
__device__ float  g_Wh[ROWS*Dd];
__device__ float4 g_q[Bb*Hh*Nn];   // {s_i, e^{s_i}, e^{0.2 s_i}, 0}
__device__ float4 g_k[Bb*Hh*Nn];
__device__ ull    g_maskbits[(size_t)ROWS*Nn/64];
__device__ float  g_hcat[ROWS*Dd];
__device__ float  g_x[ROWS*Dd];
__device__ float  g_y[ROWS*2*Dd];

// ---------------- helpers ---------------------------------------------------
__device__ __forceinline__ ull pack2(float x) {
    ull r;
    asm("mov.b64 %0, {%1, %1};" : "=l"(r) : "f"(x));
    return r;
}
__device__ __forceinline__ void fma2(ull& acc, ull ab, ull c) {
    asm("fma.rn.f32x2 %0, %1, %2, %0;" : "+l"(acc) : "l"(ab), "l"(c));
}
__device__ __forceinline__ unsigned cvt_tf32(float x) {
    unsigned r;
    asm("cvt.rna.tf32.f32 %0, %1;" : "=r"(r) : "f"(x));
    return r;
}
__device__ __forceinline__ void mma_tf32(float* d, const unsigned* a, const unsigned* b) {
    asm("mma.sync.aligned.m16n8k8.row.col.f32.tf32.tf32.f32 "
        "{%0,%1,%2,%3}, {%4,%5,%6,%7}, {%8,%9}, {%0,%1,%2,%3};"
        : "+f"(d[0]), "+f"(d[1]), "+f"(d[2]), "+f"(d[3])
        : "r"(a[0]), "r"(a[1]), "r"(a[2]), "r"(a[3]), "r"(b[0]), "r"(b[1]));
}
union F4U { float4 f4; ull u[2]; float f[4]; };

// ---------------- 1. pack mask bits + reorder W (fused) ---------------------
__global__ __launch_bounds__(256) void prep_kernel(const int4* __restrict__ adj4,
                                                   const float* __restrict__ W) {
    __shared__ unsigned char nib[256];
    int t = threadIdx.x;
    int4 v = adj4[(size_t)blockIdx.x * 256 + t];
    unsigned n = (v.x != 0) | ((v.y != 0) << 1) | ((v.z != 0) << 2) | ((v.w != 0) << 3);
    nib[t] = (unsigned char)n;
    if (blockIdx.x < 64) {
        int tid = blockIdx.x * 256 + t;      // < 16384
        int i = tid >> 7;
        int o = tid & 127;
        int hh = o >> 4, d = o & 15;
        g_Wt[tid] = W[(hh << 11) + (i << 4) + d];
    }
    __syncthreads();
    if (t < 16) {
        uint4 bytes = *(const uint4*)(nib + t * 16);
        unsigned w[4] = {bytes.x, bytes.y, bytes.z, bytes.w};
        ull word = 0;
#pragma unroll
        for (int i = 0; i < 4; i++) {
            unsigned x = w[i];
            unsigned o = (x & 0xFu) | ((x >> 4) & 0xF0u) |
                         ((x >> 8) & 0xF00u) | ((x >> 12) & 0xF000u);
            word |= (ull)o << (16 * i);
        }
        g_maskbits[(size_t)blockIdx.x * 16 + t] = word;
    }
}

// ---------------- fused 64x128-tile SGEMM (f32x2 core), 3 modes -------------
template<int MODE>
__global__ __launch_bounds__(256) void gemm_kernel(
        const float* __restrict__ A, const float* __restrict__ Bm,
        const float* __restrict__ bias, const float* __restrict__ extra,
        const float* __restrict__ gam, const float* __restrict__ bet,
        float* __restrict__ C, int K, int N) {
    __shared__ float As[16][68];
    __shared__ float Bs[16][128];
    __shared__ float sa_src[128], sa_dst[128];
    int t  = threadIdx.x;
    int tx = t & 15, ty = t >> 4;
    int row0 = blockIdx.y * 64;
    int col0 = blockIdx.x * 128;

    if (MODE == 0 && t < 128) {
        int hh = t >> 4, d = t & 15;
        sa_src[t] = extra[hh * 32 + d];
        sa_dst[t] = extra[hh * 32 + 16 + d];
    }

    ull acc2[4][4];
#pragma unroll
    for (int i = 0; i < 4; i++)
#pragma unroll
        for (int j = 0; j < 4; j++) acc2[i][j] = 0ULL;

    int arow = t >> 2, ak = (t & 3) << 2;
    for (int k0 = 0; k0 < K; k0 += 16) {
        float4 av = *(const float4*)&A[(size_t)(row0 + arow) * K + k0 + ak];
        int brow0 = t >> 5, bcol = (t & 31) << 2;
        float4 b0 = *(const float4*)&Bm[(size_t)(k0 + brow0) * N + col0 + bcol];
        float4 b1 = *(const float4*)&Bm[(size_t)(k0 + brow0 + 8) * N + col0 + bcol];
        __syncthreads();
        As[ak + 0][arow] = av.x; As[ak + 1][arow] = av.y;
        As[ak + 2][arow] = av.z; As[ak + 3][arow] = av.w;
        *(float4*)&Bs[brow0][bcol]     = b0;
        *(float4*)&Bs[brow0 + 8][bcol] = b1;
        __syncthreads();
#pragma unroll
        for (int k = 0; k < 16; k++) {
            float4 a4 = *(const float4*)&As[k][ty << 2];
            F4U q0, q1;
            q0.f4 = *(const float4*)&Bs[k][tx << 3];
            q1.f4 = *(const float4*)&Bs[k][(tx << 3) + 4];
            ull bp[4] = {q0.u[0], q0.u[1], q1.u[0], q1.u[1]};
            ull ap[4] = {pack2(a4.x), pack2(a4.y), pack2(a4.z), pack2(a4.w)};
#pragma unroll
            for (int i = 0; i < 4; i++)
#pragma unroll
                for (int j = 0; j < 4; j++) fma2(acc2[i][j], ap[i], bp[j]);
        }
    }

    float acc[4][8];
#pragma unroll
    for (int i = 0; i < 4; i++)
#pragma unroll
        for (int j = 0; j < 4; j++) {
            float2 p = *(float2*)&acc2[i][j];
            acc[i][2 * j]     = p.x;
            acc[i][2 * j + 1] = p.y;
        }

    if (MODE == 0) {
#pragma unroll
        for (int i = 0; i < 4; i++) {
            int r = row0 + (ty << 2) + i;
            *(float4*)&C[(size_t)r * 128 + (tx << 3)] =
                make_float4(acc[i][0], acc[i][1], acc[i][2], acc[i][3]);
            *(float4*)&C[(size_t)r * 128 + (tx << 3) + 4] =
                make_float4(acc[i][4], acc[i][5], acc[i][6], acc[i][7]);
            float sp = 0.f, dp = 0.f;
#pragma unroll
            for (int j = 0; j < 8; j++) {
                sp += acc[i][j] * sa_src[(tx << 3) + j];
                dp += acc[i][j] * sa_dst[(tx << 3) + j];
            }
            sp += __shfl_xor_sync(0xffffffffu, sp, 1);
            dp += __shfl_xor_sync(0xffffffffu, dp, 1);
            if (!(tx & 1)) {
                int b = r >> 10, n = r & 1023;
                int hh = tx >> 1;
                int idx = ((b << 3) + hh) * 1024 + n;
                g_q[idx] = make_float4(sp, __expf(sp), __expf(0.2f * sp), 0.f);
                g_k[idx] = make_float4(dp, __expf(dp), __expf(0.2f * dp), 0.f);
            }
        }
    } else if (MODE == 1) {
        float bv[8];
#pragma unroll
        for (int j = 0; j < 8; j++) bv[j] = bias[col0 + (tx << 3) + j];
#pragma unroll
        for (int i = 0; i < 4; i++) {
            int r = row0 + (ty << 2) + i;
            float4 r0, r1;
            r0.x = fmaxf(acc[i][0] + bv[0], 0.f); r0.y = fmaxf(acc[i][1] + bv[1], 0.f);
            r0.z = fmaxf(acc[i][2] + bv[2], 0.f); r0.w = fmaxf(acc[i][3] + bv[3], 0.f);
            r1.x = fmaxf(acc[i][4] + bv[4], 0.f); r1.y = fmaxf(acc[i][5] + bv[5], 0.f);
            r1.z = fmaxf(acc[i][6] + bv[6], 0.f); r1.w = fmaxf(acc[i][7] + bv[7], 0.f);
            *(float4*)&C[(size_t)r * N + col0 + (tx << 3)]     = r0;
            *(float4*)&C[(size_t)r * N + col0 + (tx << 3) + 4] = r1;
        }
    } else {
        float bv[8], gv[8], bb[8];
#pragma unroll
        for (int j = 0; j < 8; j++) {
            bv[j] = bias[(tx << 3) + j];
            gv[j] = gam[(tx << 3) + j];
            bb[j] = bet[(tx << 3) + j];
        }
#pragma unroll
        for (int i = 0; i < 4; i++) {
            int r = row0 + (ty << 2) + i;
            float4 x0 = *(const float4*)&extra[(size_t)r * 128 + (tx << 3)];
            float4 x1 = *(const float4*)&extra[(size_t)r * 128 + (tx << 3) + 4];
            float v[8] = {x0.x, x0.y, x0.z, x0.w, x1.x, x1.y, x1.z, x1.w};
            float s = 0.f, s2 = 0.f;
#pragma unroll
            for (int j = 0; j < 8; j++) {
                v[j] += acc[i][j] + bv[j];
                s += v[j]; s2 += v[j] * v[j];
            }
#pragma unroll
            for (int o = 1; o <= 8; o <<= 1) {
                s  += __shfl_xor_sync(0xffffffffu, s,  o);
                s2 += __shfl_xor_sync(0xffffffffu, s2, o);
            }
            float mu  = s * (1.f / 128.f);
            float var = s2 * (1.f / 128.f) - mu * mu;
            float rs  = rsqrtf(var + EPSc);
            float4 r0, r1;
            r0.x = (v[0]-mu)*rs*gv[0]+bb[0]; r0.y = (v[1]-mu)*rs*gv[1]+bb[1];
            r0.z = (v[2]-mu)*rs*gv[2]+bb[2]; r0.w = (v[3]-mu)*rs*gv[3]+bb[3];
            r1.x = (v[4]-mu)*rs*gv[4]+bb[4]; r1.y = (v[5]-mu)*rs*gv[5]+bb[5];
            r1.z = (v[6]-mu)*rs*gv[6]+bb[6]; r1.w = (v[7]-mu)*rs*gv[7]+bb[7];
            *(float4*)&C[(size_t)r * 128 + (tx << 3)]     = r0;
            *(float4*)&C[(size_t)r * 128 + (tx << 3) + 4] = r1;
        }
    }
}

// ---------------- tensor-core masked-softmax attention ----------------------
// grid (16, H, B), 128 threads = 4 warps. Warp handles 16 queries (1 m16 tile).
// P built per key-tile directly in mma A-fragment layout (fp32 bits as tf32 —
// tensor core truncates the low mantissa; no cvt in the hot loop).
// V = Wh head-slice (128k x 16) + ones column at col 16 -> MMA yields sumw free.
// weight = max(e^{si}*e^{sj}, e^{0.2si}*e^{0.2sj}), masked to 0 via bit test.
__global__ __launch_bounds__(128, 8) void att_kernel() {
    __shared__ unsigned sV[128 * 24];   // tf32 V tile, stride 24 (12 KB)
    __shared__ float2   skp[128];       // {e^sj, e^0.2sj}
    int b = blockIdx.z, hh = blockIdx.y;
    int t = threadIdx.x, l = t & 31, wp = t >> 5;
    int g = l >> 2, tig = l & 3;
    int bN = b * Nn, bhN = (b * Hh + hh) * Nn;
    int qbase = blockIdx.x * 64 + wp * 16;

    int q0i = qbase + g, q1i = qbase + g + 8;
    float4 v0q = g_q[bhN + q0i];
    float4 v1q = g_q[bhN + q1i];
    float E1a = v0q.y, E2a = v0q.z;
    float E1b = v1q.y, E2b = v1q.z;
    size_t mro0 = (size_t)(bN + q0i) * 16;
    size_t mro1 = (size_t)(bN + q1i) * 16;
    unsigned bitA = 1u << tig, bitB = 1u << (tig + 4);

    float d[3][4];
#pragma unroll
    for (int n = 0; n < 3; n++)
#pragma unroll
        for (int c = 0; c < 4; c++) d[n][c] = 0.f;

    for (int kt = 0; kt < 8; kt++) {
        __syncthreads();
        {   // stage V + kp: thread t owns key row kt*128 + t
            int key = kt * 128 + t;
            const float4* wr = (const float4*)&g_Wh[(size_t)(bN + key) * 128 + (hh << 4)];
            float4 v0 = wr[0], v1 = wr[1], v2 = wr[2], v3 = wr[3];
            unsigned* dst = &sV[t * 24];
            *(uint4*)&dst[0]  = make_uint4(cvt_tf32(v0.x), cvt_tf32(v0.y), cvt_tf32(v0.z), cvt_tf32(v0.w));
            *(uint4*)&dst[4]  = make_uint4(cvt_tf32(v1.x), cvt_tf32(v1.y), cvt_tf32(v1.z), cvt_tf32(v1.w));
            *(uint4*)&dst[8]  = make_uint4(cvt_tf32(v2.x), cvt_tf32(v2.y), cvt_tf32(v2.z), cvt_tf32(v2.w));
            *(uint4*)&dst[12] = make_uint4(cvt_tf32(v3.x), cvt_tf32(v3.y), cvt_tf32(v3.z), cvt_tf32(v3.w));
            *(uint4*)&dst[16] = make_uint4(0x3f800000u, 0u, 0u, 0u);   // ones col + zeros
            *(uint4*)&dst[20] = make_uint4(0u, 0u, 0u, 0u);
            float4 kv = g_k[bhN + key];
            skp[t] = make_float2(kv.y, kv.z);
        }
        __syncthreads();

#pragma unroll
        for (int half = 0; half < 2; half++) {
            ull cur0 = g_maskbits[mro0 + 2 * kt + half];
            ull cur1 = g_maskbits[mro1 + 2 * kt + half];
#pragma unroll
            for (int ks = 0; ks < 8; ks++) {
                int krow = half * 64 + ks * 8;
                unsigned bfr[3][2];
#pragma unroll
                for (int n = 0; n < 3; n++) {
                    bfr[n][0] = sV[(krow + tig) * 24 + n * 8 + g];
                    bfr[n][1] = sV[(krow + tig + 4) * 24 + n * 8 + g];
                }
                float2 kp0 = skp[krow + tig];
                float2 kp1 = skp[krow + tig + 4];

                unsigned c0 = (unsigned)cur0;
                unsigned c1 = (unsigned)cur1;
                float w00 = fmaxf(E1a * kp0.x, E2a * kp0.y);
                float w10 = fmaxf(E1b * kp0.x, E2b * kp0.y);
                float w01 = fmaxf(E1a * kp1.x, E2a * kp1.y);
                float w11 = fmaxf(E1b * kp1.x, E2b * kp1.y);
                w00 = (c0 & bitA) ? w00 : 0.f;
                w10 = (c1 & bitA) ? w10 : 0.f;
                w01 = (c0 & bitB) ? w01 : 0.f;
                w11 = (c1 & bitB) ? w11 : 0.f;
                unsigned a[4] = {__float_as_uint(w00), __float_as_uint(w10),
                                 __float_as_uint(w01), __float_as_uint(w11)};
                mma_tf32(d[0], a, bfr[0]);
                mma_tf32(d[1], a, bfr[1]);
                mma_tf32(d[2], a, bfr[2]);
                cur0 >>= 8;
                cur1 >>= 8;
            }
        }
    }

    // epilogue: sumw is D column 16 (ntile2, local col 0 -> tig==0 lanes)
    float sw0 = __shfl_sync(0xffffffffu, d[2][0], l & ~3);
    float sw1 = __shfl_sync(0xffffffffu, d[2][2], l & ~3);
    float inv0 = (sw0 > 0.f) ? __fdividef(1.f, sw0) : 0.f;
    float inv1 = (sw1 > 0.f) ? __fdividef(1.f, sw1) : 0.f;
    float* r0 = &g_hcat[(size_t)(bN + q0i) * 128 + (hh << 4)];
    float* r1 = &g_hcat[(size_t)(bN + q1i) * 128 + (hh << 4)];
    *(float2*)&r0[2*tig]     = make_float2(d[0][0] * inv0, d[0][1] * inv0);
    *(float2*)&r0[8 + 2*tig] = make_float2(d[1][0] * inv0, d[1][1] * inv0);
    *(float2*)&r1[2*tig]     = make_float2(d[0][2] * inv1, d[0][3] * inv1);
    *(float2*)&r1[8 + 2*tig] = make_float2(d[1][2] * inv1, d[1][3] * inv1);
}

// ---------------- LN1: warp-per-row, float4, shuffle-only reduce ------------
__global__ __launch_bounds__(256) void ln_kernel(
        const float* __restrict__ A, const float* __restrict__ R,
        const float* __restrict__ g, const float* __restrict__ bta,
        float* __restrict__ out) {
    int wp = threadIdx.x >> 5, l = threadIdx.x & 31;
    int row = blockIdx.x * 8 + wp;
    size_t base = (size_t)row * Dd + (l << 2);
    float4 a4 = *(const float4*)&A[base];
    float4 r4 = *(const float4*)&R[base];
    float v[4] = {a4.x + r4.x, a4.y + r4.y, a4.z + r4.z, a4.w + r4.w};
    float s = v[0] + v[1] + v[2] + v[3];
    float s2 = v[0]*v[0] + v[1]*v[1] + v[2]*v[2] + v[3]*v[3];
#pragma unroll
    for (int o = 16; o > 0; o >>= 1) {
        s  += __shfl_xor_sync(0xffffffffu, s,  o);
        s2 += __shfl_xor_sync(0xffffffffu, s2, o);
    }
    float mu  = s * (1.f / Dd);
    float var = s2 * (1.f / Dd) - mu * mu;
    float rs = rsqrtf(var + EPSc);
    float4 g4 = *(const float4*)&g[l << 2];
    float4 b4 = *(const float4*)&bta[l << 2];
    float4 o4;
    o4.x = (v[0]-mu)*rs*g4.x + b4.x; o4.y = (v[1]-mu)*rs*g4.y + b4.y;
    o4.z = (v[2]-mu)*rs*g4.z + b4.z; o4.w = (v[3]-mu)*rs*g4.w + b4.w;
    *(float4*)&out[base] = o4;
}

// ---------------- launch ----------------------------------------------------
extern "C" void kernel_launch(void* const* d_in, const int* in_sizes, int n_in,
                              void* d_out, int out_size) {
    const float* h    = (const float*)d_in[0];
    const int*   adj  = (const int*)d_in[1];
    const float* W    = (const float*)d_in[2];
    const float* a    = (const float*)d_in[3];
    const float* ln1g = (const float*)d_in[4];
    const float* ln1b = (const float*)d_in[5];
    const float* w1   = (const float*)d_in[6];
    const float* b1   = (const float*)d_in[7];
    const float* w2   = (const float*)d_in[8];
    const float* b2   = (const float*)d_in[9];
    const float* ln2g = (const float*)d_in[10];
    const float* ln2b = (const float*)d_in[11];
    float* out = (float*)d_out;

    float *Wt, *Wh, *hcat, *x, *y;
    cudaGetSymbolAddress((void**)&Wt,   g_Wt);
    cudaGetSymbolAddress((void**)&Wh,   g_Wh);
    cudaGetSymbolAddress((void**)&hcat, g_hcat);
    cudaGetSymbolAddress((void**)&x,    g_x);
    cudaGetSymbolAddress((void**)&y,    g_y);

    // mask pack + W reorder (fused)
    prep_kernel<<<(Bb * Nn * Nn) / 1024, 256>>>((const int4*)adj, W);
    // Wh + score/exp tables (fused)
    gemm_kernel<0><<<dim3(1, ROWS / 64), 256>>>(h, Wt, nullptr, a, nullptr, nullptr,
                                                Wh, Dd, Dd);
    // attention (tensor-core, 64-query blocks)
    att_kernel<<<dim3(Nn / 64, Hh, Bb), 128>>>();
    // LN1(hcat + h) -> x
    ln_kernel<<<ROWS / 8, 256>>>(hcat, h, ln1g, ln1b, x);
    // y = relu(x @ w1 + b1)
    gemm_kernel<1><<<dim3(2, ROWS / 64), 256>>>(x, w1, b1, nullptr, nullptr, nullptr,
                                                y, Dd, 2 * Dd);
    // out = LN2(x + y @ w2 + b2)
    gemm_kernel<2><<<dim3(1, ROWS / 64), 256>>>(y, w2, b2, x, ln2g, ln2b,
                                                out, 2 * Dd, Dd);
}